// round 10
// baseline (speedup 1.0000x reference)
#include <cuda_runtime.h>
#include <cuda_bf16.h>
#include <math.h>
#include <cstdint>

// Problem constants
#define T_STEPS 256
#define BSZ     64
#define DIM     1024
#define N3      (3 * DIM)          // 3072
#define M_TOTAL (T_STEPS * BSZ)    // 16384
#define NCTA    128
#define NTHR    256

typedef unsigned long long ull;

// Scratch (__device__ globals; allocation-free rule)
__device__ float g_xproj[(size_t)M_TOTAL * N3];             // [T,B,3D] ~192 MiB
__device__ __nv_bfloat16 g_hh[BSZ * DIM];                   // h hi split
__device__ __nv_bfloat16 g_hl[BSZ * DIM];                   // h lo split
__device__ __nv_bfloat16 g_ins_hi[(size_t)M_TOTAL * DIM];   // 32 MiB
__device__ __nv_bfloat16 g_ins_lo[(size_t)M_TOTAL * DIM];   // 32 MiB
__device__ __nv_bfloat16 g_wi_hi[(size_t)N3 * DIM];         // W_i [N,K]
__device__ __nv_bfloat16 g_wi_lo[(size_t)N3 * DIM];
__device__ __nv_bfloat16 g_wh_hi[(size_t)N3 * DIM];         // W_h [N,K]
__device__ __nv_bfloat16 g_wh_lo[(size_t)N3 * DIM];
__device__ int   g_dones_is_byte;
__device__ unsigned g_bar_count;
__device__ unsigned g_bar_epoch;

__device__ __forceinline__ uint32_t smem_u32(const void* p) {
    uint32_t a;
    asm("{ .reg .u64 t; cvta.to.shared.u64 t, %1; cvt.u32.u64 %0, t; }"
        : "=r"(a) : "l"(p));
    return a;
}

// ---------------- dones dtype probe ----------------
__global__ void detect_dones_kernel(const unsigned char* __restrict__ p) {
    int nz = 0;
    for (int i = 0; i < 256; i++)
        if ((i & 3) != 0 && p[i] != 0) nz++;
    g_dones_is_byte = (nz > 0) ? 1 : 0;
}
__device__ __forceinline__ bool read_done(const void* dones, int idx, int is_byte) {
    if (is_byte) return ((const unsigned char*)dones)[idx] != 0;
    return ((const int*)dones)[idx] != 0;
}

// ---------------- bf16 split conversions ----------------
__global__ __launch_bounds__(256) void convert_ins_kernel(const float* __restrict__ A) {
    size_t i = ((size_t)blockIdx.x * 256 + threadIdx.x) * 4;
    float4 v = *(const float4*)(A + i);
    __nv_bfloat16 h0 = __float2bfloat16_rn(v.x);
    __nv_bfloat16 h1 = __float2bfloat16_rn(v.y);
    __nv_bfloat16 h2 = __float2bfloat16_rn(v.z);
    __nv_bfloat16 h3 = __float2bfloat16_rn(v.w);
    __nv_bfloat16 l0 = __float2bfloat16_rn(v.x - __bfloat162float(h0));
    __nv_bfloat16 l1 = __float2bfloat16_rn(v.y - __bfloat162float(h1));
    __nv_bfloat16 l2 = __float2bfloat16_rn(v.z - __bfloat162float(h2));
    __nv_bfloat16 l3 = __float2bfloat16_rn(v.w - __bfloat162float(h3));
    __nv_bfloat162* hp = (__nv_bfloat162*)(g_ins_hi + i);
    __nv_bfloat162* lp = (__nv_bfloat162*)(g_ins_lo + i);
    hp[0] = __nv_bfloat162(h0, h1); hp[1] = __nv_bfloat162(h2, h3);
    lp[0] = __nv_bfloat162(l0, l1); lp[1] = __nv_bfloat162(l2, l3);
}

// [K,N3] f32 -> [N3,K] bf16 hi/lo, 32x32 SMEM tile transpose
__global__ __launch_bounds__(256) void convert_w_kernel(
    const float* __restrict__ W, __nv_bfloat16* __restrict__ hi,
    __nv_bfloat16* __restrict__ lo)
{
    __shared__ float tile[32][33];
    const int nb = blockIdx.x * 32;
    const int kb = blockIdx.y * 32;
    const int c = threadIdx.x & 31;
    const int r8 = threadIdx.x >> 5;
#pragma unroll
    for (int s = 0; s < 4; s++) {
        int r = r8 + s * 8;
        tile[r][c] = W[(size_t)(kb + r) * N3 + nb + c];
    }
    __syncthreads();
#pragma unroll
    for (int s = 0; s < 4; s++) {
        int r = r8 + s * 8;
        float v = tile[c][r];
        __nv_bfloat16 h = __float2bfloat16_rn(v);
        __nv_bfloat16 l = __float2bfloat16_rn(v - __bfloat162float(h));
        size_t o = (size_t)(nb + r) * DIM + kb + c;
        hi[o] = h;
        lo[o] = l;
    }
}

// ---------------- HMMA primitives ----------------
__device__ __forceinline__ void ldsm_x4(uint32_t addr, uint32_t* r) {
    asm volatile("ldmatrix.sync.aligned.m8n8.x4.shared.b16 {%0,%1,%2,%3}, [%4];"
                 : "=r"(r[0]), "=r"(r[1]), "=r"(r[2]), "=r"(r[3]) : "r"(addr));
}
__device__ __forceinline__ void ldsm_x2(uint32_t addr, uint32_t* r) {
    asm volatile("ldmatrix.sync.aligned.m8n8.x2.shared.b16 {%0,%1}, [%2];"
                 : "=r"(r[0]), "=r"(r[1]) : "r"(addr));
}
__device__ __forceinline__ void mma16816(float* c, const uint32_t* a,
                                         uint32_t b0, uint32_t b1) {
    asm volatile(
        "mma.sync.aligned.m16n8k16.row.col.f32.bf16.bf16.f32 "
        "{%0,%1,%2,%3}, {%4,%5,%6,%7}, {%8,%9}, {%0,%1,%2,%3};"
        : "+f"(c[0]), "+f"(c[1]), "+f"(c[2]), "+f"(c[3])
        : "r"(a[0]), "r"(a[1]), "r"(a[2]), "r"(a[3]), "r"(b0), "r"(b1));
}

// ---------------------------------------------------------------------------
// HMMA xproj (proven): g_xproj = ins @ W_i + b_i, bf16x3.
// ---------------------------------------------------------------------------
#define XSTRIDE 40

__global__ __launch_bounds__(256, 1) void gemm_xproj_mma_kernel(
    const float* __restrict__ bias)
{
    __shared__ __align__(16) __nv_bfloat16 As[2][128 * XSTRIDE];
    __shared__ __align__(16) __nv_bfloat16 Bs[2][128 * XSTRIDE];

    const int tid = threadIdx.x;
    const int wid = tid >> 5;
    const int lane = tid & 31;
    const int wm = wid >> 2;
    const int wn = wid & 3;
    const int bn = blockIdx.x;
    const int bm = blockIdx.y;

    const __nv_bfloat16* Ahi = g_ins_hi + (size_t)bm * 128 * DIM;
    const __nv_bfloat16* Alo = g_ins_lo + (size_t)bm * 128 * DIM;
    const __nv_bfloat16* Bhi = g_wi_hi + (size_t)bn * 128 * DIM;
    const __nv_bfloat16* Blo = g_wi_lo + (size_t)bn * 128 * DIM;

    const int c0 = tid, c1 = tid + 256;
    const int m0 = c0 >> 2, kc0 = c0 & 3;
    const int m1 = c1 >> 2, kc1 = c1 & 3;

    const int a_off = (wm * 64 + (lane & 15)) * XSTRIDE + (lane >> 4) * 8;
    const int b_off = (wn * 32 + (lane & 7) + ((lane >> 4) & 1) * 8) * XSTRIDE
                      + ((lane >> 3) & 1) * 8;

    float acc[4][4][4];
#pragma unroll
    for (int i = 0; i < 4; i++)
#pragma unroll
        for (int j = 0; j < 4; j++)
#pragma unroll
            for (int q = 0; q < 4; q++) acc[i][j][q] = 0.f;

    uint4 pa0, pa1, pb0, pb1;
    pa0 = *(const uint4*)(Ahi + (size_t)m0 * DIM + kc0 * 8);
    pa1 = *(const uint4*)(Ahi + (size_t)m1 * DIM + kc1 * 8);
    pb0 = *(const uint4*)(Bhi + (size_t)m0 * DIM + kc0 * 8);
    pb1 = *(const uint4*)(Bhi + (size_t)m1 * DIM + kc1 * 8);
    *(uint4*)&As[0][m0 * XSTRIDE + kc0 * 8] = pa0;
    *(uint4*)&As[0][m1 * XSTRIDE + kc1 * 8] = pa1;
    *(uint4*)&Bs[0][m0 * XSTRIDE + kc0 * 8] = pb0;
    *(uint4*)&Bs[0][m1 * XSTRIDE + kc1 * 8] = pb1;
    __syncthreads();

    int cur = 0;
    for (int kt = 0; kt < 96; kt++) {
        if (kt + 1 < 96) {
            int nt = kt + 1;
            int pass = nt >> 5;
            int k0 = (nt & 31) * 32;
            const __nv_bfloat16* Ap = (pass < 2) ? Ahi : Alo;
            const __nv_bfloat16* Bp = (pass == 1) ? Blo : Bhi;
            pa0 = *(const uint4*)(Ap + (size_t)m0 * DIM + k0 + kc0 * 8);
            pa1 = *(const uint4*)(Ap + (size_t)m1 * DIM + k0 + kc1 * 8);
            pb0 = *(const uint4*)(Bp + (size_t)m0 * DIM + k0 + kc0 * 8);
            pb1 = *(const uint4*)(Bp + (size_t)m1 * DIM + k0 + kc1 * 8);
        }

        const uint32_t a_base = smem_u32(&As[cur][0]) + a_off * 2;
        const uint32_t b_base = smem_u32(&Bs[cur][0]) + b_off * 2;
#pragma unroll
        for (int ks = 0; ks < 2; ks++) {
            uint32_t af[4][4], bf[2][4];
#pragma unroll
            for (int i = 0; i < 4; i++)
                ldsm_x4(a_base + (i * 16 * XSTRIDE + ks * 16) * 2, af[i]);
#pragma unroll
            for (int jj = 0; jj < 2; jj++)
                ldsm_x4(b_base + (jj * 16 * XSTRIDE + ks * 16) * 2, bf[jj]);
#pragma unroll
            for (int i = 0; i < 4; i++)
#pragma unroll
                for (int j = 0; j < 4; j++)
                    mma16816(acc[i][j], af[i],
                             bf[j >> 1][(j & 1) * 2], bf[j >> 1][(j & 1) * 2 + 1]);
        }

        if (kt + 1 < 96) {
            int nxt = cur ^ 1;
            *(uint4*)&As[nxt][m0 * XSTRIDE + kc0 * 8] = pa0;
            *(uint4*)&As[nxt][m1 * XSTRIDE + kc1 * 8] = pa1;
            *(uint4*)&Bs[nxt][m0 * XSTRIDE + kc0 * 8] = pb0;
            *(uint4*)&Bs[nxt][m1 * XSTRIDE + kc1 * 8] = pb1;
        }
        __syncthreads();
        cur ^= 1;
    }

    const int groupID = lane >> 2, tig = lane & 3;
#pragma unroll
    for (int i = 0; i < 4; i++) {
        int mrow = bm * 128 + wm * 64 + i * 16 + groupID;
        float* row0 = g_xproj + (size_t)mrow * N3;
        float* row1 = g_xproj + (size_t)(mrow + 8) * N3;
#pragma unroll
        for (int j = 0; j < 4; j++) {
            int ncol = bn * 128 + wn * 32 + j * 8 + tig * 2;
            float2 bv = *(const float2*)&bias[ncol];
            float2 o0, o1;
            o0.x = acc[i][j][0] + bv.x; o0.y = acc[i][j][1] + bv.y;
            o1.x = acc[i][j][2] + bv.x; o1.y = acc[i][j][3] + bv.y;
            *(float2*)&row0[ncol] = o0;
            *(float2*)&row1[ncol] = o1;
        }
    }
}

// ---------------------------------------------------------------------------
// Grid barrier (proven R8): syncthreads + leader release-atomic / acquire-poll.
// ---------------------------------------------------------------------------
__device__ __forceinline__ void grid_barrier(unsigned* s_epoch, bool last) {
    __syncthreads();
    if (threadIdx.x == 0) {
        unsigned my = *s_epoch;
        unsigned prev;
        asm volatile("atom.release.gpu.add.u32 %0, [%1], 1;"
                     : "=r"(prev) : "l"(&g_bar_count) : "memory");
        if (prev == NCTA - 1) {
            g_bar_count = 0;
            asm volatile("st.release.gpu.u32 [%0], %1;"
                         :: "l"(&g_bar_epoch), "r"(last ? 0u : (my + 1u))
                         : "memory");
        } else {
            unsigned e;
            do {
                __nanosleep(32);
                asm volatile("ld.acquire.gpu.u32 %0, [%1];"
                             : "=r"(e) : "l"(&g_bar_epoch) : "memory");
            } while (e == my);
        }
        *s_epoch = my + 1u;
    }
    __syncthreads();
}

// ---------------------------------------------------------------------------
// Persistent scan, no split-K: each CTA owns 8 d-columns (24 W rows, full K),
// W slice hi/lo resident in SMEM; ONE grid barrier per step.
// Warps: 4 m-tiles (m16) x 2 k-halves; k-half partials reduced via SMEM.
// ---------------------------------------------------------------------------
#define XSW 1032              // W row stride (elems): 2064B = 516 words, 516%32=4
#define XSH 136               // h row stride (elems): 272B = 68 words, 68%32=4
#define SM_W_HI 0
#define SM_W_LO (24 * XSW)                   // 24768
#define SM_H    (48 * XSW)                   // 49536
#define HBUF_STRIDE (2 * 64 * XSH)           // 17408 elems per buffer (hi+lo)
#define HLO_OFF (64 * XSH)                   // 8704
#define SCAN_SMEM ((SM_H + 2 * HBUF_STRIDE) * 2)   // 168704 B

__global__ __launch_bounds__(NTHR, 1) void scan_kernel(
    const float* __restrict__ hiddens,
    const void*  __restrict__ dones,
    const float* __restrict__ init_carry,
    const float* __restrict__ b_hn,
    float* __restrict__ out)
{
    extern __shared__ __nv_bfloat16 sm[];
    __shared__ float hprev[BSZ][8];
    __shared__ unsigned s_epoch;

    const int tid = threadIdx.x;
    const int cta = blockIdx.x;
    const int d0 = cta * 8;              // owned d-columns d0..d0+7
    const int wid = tid >> 5;
    const int lane = tid & 31;
    const int wm = wid >> 1;             // 0..3 m16 tile
    const int kh = wid & 1;              // k-half within each chunk
    const int is_byte = g_dones_is_byte;
    float* ys = out + (size_t)BSZ * DIM;
    float* red = (float*)(sm + SM_H);    // overlay on h buffer 0 (after MMA done)

    if (tid == 0) s_epoch = 0;

    // W_h slice -> SMEM once: rows j=0..23 -> gate j>>3, col d0+(j&7)
    for (int i = tid; i < 24 * 128; i += NTHR) {
        int row = i >> 7;                // 0..23
        int ku = i & 127;                // uint4 index within row
        int grow = (row >> 3) * DIM + d0 + (row & 7);
        size_t go = (size_t)grow * DIM + ku * 8;
        *(uint4*)&sm[SM_W_HI + row * XSW + ku * 8] = *(const uint4*)&g_wh_hi[go];
        *(uint4*)&sm[SM_W_LO + row * XSW + ku * 8] = *(const uint4*)&g_wh_lo[go];
    }

    // phase-B element mapping: 2 outputs per thread, (b, dl) with dl even
    const int pb_b = tid >> 2;
    const int pb_dl = (tid & 3) * 2;

    // init h_eff (t=0 reset applied) for owned slice
    {
        bool dn = read_done(dones, pb_b, is_byte);
        const float* src = dn ? (hiddens + (size_t)pb_b * DIM)
                              : (init_carry + (size_t)pb_b * DIM);
        float2 v = *(const float2*)&src[d0 + pb_dl];
        hprev[pb_b][pb_dl] = v.x;
        hprev[pb_b][pb_dl + 1] = v.y;
        __nv_bfloat16 h0 = __float2bfloat16_rn(v.x);
        __nv_bfloat16 h1 = __float2bfloat16_rn(v.y);
        __nv_bfloat16 l0 = __float2bfloat16_rn(v.x - __bfloat162float(h0));
        __nv_bfloat16 l1 = __float2bfloat16_rn(v.y - __bfloat162float(h1));
        *(__nv_bfloat162*)&g_hh[pb_b * DIM + d0 + pb_dl] = __nv_bfloat162(h0, h1);
        *(__nv_bfloat162*)&g_hl[pb_b * DIM + d0 + pb_dl] = __nv_bfloat162(l0, l1);
    }
    grid_barrier(&s_epoch, false);

    // lane-static ldsm offsets (elems)
    const int a_static = (wm * 16 + (lane & 15)) * XSH + (lane >> 4) * 8 + kh * 64;
    const int b4_static = ((lane & 7) + ((lane >> 4) & 1) * 8) * XSW
                          + ((lane >> 3) & 1) * 8;
    const int b2_static = (16 + (lane & 7)) * XSW + ((lane >> 3) & 1) * 8;
    const int groupID = lane >> 2, tig = lane & 3;

    // staging coords: 4 consecutive uint4 per thread per array
    const int st_row = tid >> 2;         // 0..63
    const int st_kc = (tid & 3) * 32;    // elem offset within 128-chunk

    const uint32_t smb = smem_u32(sm);

    for (int t = 0; t < T_STEPS; t++) {
        // prefetch xproj for phase B (independent of everything this step)
        const float* xp = g_xproj + ((size_t)t * BSZ + pb_b) * N3;
        float2 xr = __ldcg((const float2*)&xp[d0 + pb_dl]);
        float2 xz = __ldcg((const float2*)&xp[DIM + d0 + pb_dl]);
        float2 xn = __ldcg((const float2*)&xp[2 * DIM + d0 + pb_dl]);

        float acc[3][4];
#pragma unroll
        for (int j = 0; j < 3; j++)
#pragma unroll
            for (int q = 0; q < 4; q++) acc[j][q] = 0.f;

        // prefetch chunk 0 and store to buf 0
        uint4 ph[4], pl[4];
        {
            const __nv_bfloat16* hh = g_hh + (size_t)st_row * DIM + st_kc;
            const __nv_bfloat16* hl = g_hl + (size_t)st_row * DIM + st_kc;
#pragma unroll
            for (int u = 0; u < 4; u++) {
                ph[u] = __ldcg((const uint4*)(hh + u * 8));
                pl[u] = __ldcg((const uint4*)(hl + u * 8));
            }
#pragma unroll
            for (int u = 0; u < 4; u++) {
                *(uint4*)&sm[SM_H + st_row * XSH + st_kc + u * 8] = ph[u];
                *(uint4*)&sm[SM_H + HLO_OFF + st_row * XSH + st_kc + u * 8] = pl[u];
            }
        }

        for (int c = 0; c < 8; c++) {
            __syncthreads();             // buf[c&1] visible; prior MMA complete
            if (c < 8 - 1) {
                const __nv_bfloat16* hh =
                    g_hh + (size_t)st_row * DIM + (c + 1) * 128 + st_kc;
                const __nv_bfloat16* hl =
                    g_hl + (size_t)st_row * DIM + (c + 1) * 128 + st_kc;
#pragma unroll
                for (int u = 0; u < 4; u++) {
                    ph[u] = __ldcg((const uint4*)(hh + u * 8));
                    pl[u] = __ldcg((const uint4*)(hl + u * 8));
                }
            }

            const uint32_t hbuf = SM_H + (c & 1) * HBUF_STRIDE;
            const int kpos = c * 128 + kh * 64;
#pragma unroll
            for (int pass = 0; pass < 3; pass++) {
                const uint32_t ab = smb +
                    (hbuf + (pass == 1 ? HLO_OFF : 0) + a_static) * 2;
                const uint32_t wsel = (pass == 2) ? SM_W_LO : SM_W_HI;
                const uint32_t bb4 = smb + (wsel + b4_static + kpos) * 2;
                const uint32_t bb2 = smb + (wsel + b2_static + kpos) * 2;
#pragma unroll
                for (int ks = 0; ks < 4; ks++) {
                    uint32_t af[4], b4[4], b2[2];
                    ldsm_x4(ab + ks * 32, af);
                    ldsm_x4(bb4 + ks * 32, b4);
                    ldsm_x2(bb2 + ks * 32, b2);
                    mma16816(acc[0], af, b4[0], b4[1]);
                    mma16816(acc[1], af, b4[2], b4[3]);
                    mma16816(acc[2], af, b2[0], b2[1]);
                }
            }

            if (c < 8 - 1) {
                const uint32_t nb = SM_H + ((c + 1) & 1) * HBUF_STRIDE;
#pragma unroll
                for (int u = 0; u < 4; u++) {
                    *(uint4*)&sm[nb + st_row * XSH + st_kc + u * 8] = ph[u];
                    *(uint4*)&sm[nb + HLO_OFF + st_row * XSH + st_kc + u * 8] = pl[u];
                }
            }
        }
        __syncthreads();                 // all MMA done; safe to overlay red

        // write k-half partials: red[kh][wm][row16][24]
        {
            float* base = red + ((kh * 4 + wm) * 16) * 24;
#pragma unroll
            for (int j = 0; j < 3; j++) {
                int col = j * 8 + tig * 2;
                *(float2*)&base[groupID * 24 + col] =
                    make_float2(acc[j][0], acc[j][1]);
                *(float2*)&base[(groupID + 8) * 24 + col] =
                    make_float2(acc[j][2], acc[j][3]);
            }
        }
        __syncthreads();

        // ---- phase B: gates for owned slice (b = pb_b, d = d0 + pb_dl..+1)
        {
            const int mt = pb_b >> 4, row = pb_b & 15;
            const float* r0 = red + ((0 + mt) * 16 + row) * 24;
            const float* r1 = red + ((4 + mt) * 16 + row) * 24;
            float2 hr, hz, hn2;
            {
                float2 a0 = *(const float2*)&r0[pb_dl];
                float2 a1 = *(const float2*)&r1[pb_dl];
                hr.x = a0.x + a1.x; hr.y = a0.y + a1.y;
                a0 = *(const float2*)&r0[8 + pb_dl];
                a1 = *(const float2*)&r1[8 + pb_dl];
                hz.x = a0.x + a1.x; hz.y = a0.y + a1.y;
                a0 = *(const float2*)&r0[16 + pb_dl];
                a1 = *(const float2*)&r1[16 + pb_dl];
                hn2.x = a0.x + a1.x; hn2.y = a0.y + a1.y;
            }
            float2 h2 = *(const float2*)&hprev[pb_b][pb_dl];
            float2 bh = *(const float2*)&b_hn[d0 + pb_dl];

            float rx = 1.f / (1.f + __expf(-(xr.x + hr.x)));
            float ry = 1.f / (1.f + __expf(-(xr.y + hr.y)));
            float zx = 1.f / (1.f + __expf(-(xz.x + hz.x)));
            float zy = 1.f / (1.f + __expf(-(xz.y + hz.y)));
            float nx = tanhf(xn.x + rx * (hn2.x + bh.x));
            float ny = tanhf(xn.y + ry * (hn2.y + bh.y));
            float2 hnew;
            hnew.x = (1.f - zx) * nx + zx * h2.x;
            hnew.y = (1.f - zy) * ny + zy * h2.y;

            *(float2*)&ys[((size_t)t * BSZ + pb_b) * DIM + d0 + pb_dl] = hnew;
            if (t == T_STEPS - 1) {
                *(float2*)&out[pb_b * DIM + d0 + pb_dl] = hnew;
            } else {
                bool dn = read_done(dones, (t + 1) * BSZ + pb_b, is_byte);
                float2 he = hnew;
                if (dn)
                    he = *(const float2*)
                        &hiddens[((size_t)(t + 1) * BSZ + pb_b) * DIM + d0 + pb_dl];
                hprev[pb_b][pb_dl] = he.x;
                hprev[pb_b][pb_dl + 1] = he.y;
                __nv_bfloat16 h0 = __float2bfloat16_rn(he.x);
                __nv_bfloat16 h1 = __float2bfloat16_rn(he.y);
                __nv_bfloat16 l0 = __float2bfloat16_rn(he.x - __bfloat162float(h0));
                __nv_bfloat16 l1 = __float2bfloat16_rn(he.y - __bfloat162float(h1));
                *(__nv_bfloat162*)&g_hh[pb_b * DIM + d0 + pb_dl] =
                    __nv_bfloat162(h0, h1);
                *(__nv_bfloat162*)&g_hl[pb_b * DIM + d0 + pb_dl] =
                    __nv_bfloat162(l0, l1);
            }
        }
        grid_barrier(&s_epoch, t == T_STEPS - 1);
    }
}

// ---------------------------------------------------------------------------
extern "C" void kernel_launch(void* const* d_in, const int* in_sizes, int n_in,
                              void* d_out, int out_size) {
    const float* ins        = (const float*)d_in[0];
    const float* hiddens    = (const float*)d_in[1];
    const void*  dones      = d_in[2];
    const float* init_carry = (const float*)d_in[3];
    const float* W_i        = (const float*)d_in[4];
    const float* W_h        = (const float*)d_in[5];
    const float* b_i        = (const float*)d_in[6];
    const float* b_hn       = (const float*)d_in[7];
    float* out = (float*)d_out;

    __nv_bfloat16 *wi_hi_p, *wi_lo_p, *wh_hi_p, *wh_lo_p;
    cudaGetSymbolAddress((void**)&wi_hi_p, g_wi_hi);
    cudaGetSymbolAddress((void**)&wi_lo_p, g_wi_lo);
    cudaGetSymbolAddress((void**)&wh_hi_p, g_wh_hi);
    cudaGetSymbolAddress((void**)&wh_lo_p, g_wh_lo);

    cudaFuncSetAttribute(scan_kernel,
                         cudaFuncAttributeMaxDynamicSharedMemorySize, SCAN_SMEM);

    detect_dones_kernel<<<1, 1>>>((const unsigned char*)dones);

    convert_ins_kernel<<<(int)(((size_t)M_TOTAL * DIM / 4) / 256), 256>>>(ins);
    {
        dim3 gw(N3 / 32, DIM / 32);
        convert_w_kernel<<<gw, 256>>>(W_i, wi_hi_p, wi_lo_p);
        convert_w_kernel<<<gw, 256>>>(W_h, wh_hi_p, wh_lo_p);
    }

    {
        dim3 grid(N3 / 128, M_TOTAL / 128);   // (24, 128)
        gemm_xproj_mma_kernel<<<grid, 256>>>(b_i);
    }

    scan_kernel<<<NCTA, NTHR, SCAN_SMEM>>>(hiddens, dones, init_carry, b_hn, out);
}

// round 13
// speedup vs baseline: 1.2794x; 1.2794x over previous
#include <cuda_runtime.h>
#include <cuda_bf16.h>
#include <math.h>
#include <cstdint>

// Problem constants
#define T_STEPS 256
#define BSZ     64
#define DIM     1024
#define N3      (3 * DIM)          // 3072
#define M_TOTAL (T_STEPS * BSZ)    // 16384
#define NCTA    128
#define NTHR    256

typedef unsigned long long ull;

// Scratch (__device__ globals; allocation-free rule)
__device__ float g_xproj[(size_t)M_TOTAL * N3];             // [T,B,3D] ~192 MiB
__device__ float g_part[4 * BSZ * N3];                      // split-K partials
__device__ __nv_bfloat16 g_hh[BSZ * DIM];                   // h hi split
__device__ __nv_bfloat16 g_hl[BSZ * DIM];                   // h lo split
__device__ __nv_bfloat16 g_ins_hi[(size_t)M_TOTAL * DIM];   // 32 MiB
__device__ __nv_bfloat16 g_ins_lo[(size_t)M_TOTAL * DIM];   // 32 MiB
__device__ __nv_bfloat16 g_wi_hi[(size_t)N3 * DIM];         // W_i [N,K]
__device__ __nv_bfloat16 g_wi_lo[(size_t)N3 * DIM];
__device__ __nv_bfloat16 g_wh_hi[(size_t)N3 * DIM];         // W_h [N,K]
__device__ __nv_bfloat16 g_wh_lo[(size_t)N3 * DIM];
__device__ int   g_dones_is_byte;
__device__ unsigned g_bar[128];     // [0]=count, [64]=epoch (separate 256B lines)

__device__ __forceinline__ uint32_t smem_u32(const void* p) {
    uint32_t a;
    asm("{ .reg .u64 t; cvta.to.shared.u64 t, %1; cvt.u32.u64 %0, t; }"
        : "=r"(a) : "l"(p));
    return a;
}

// ---------------- dones dtype probe ----------------
__global__ void detect_dones_kernel(const unsigned char* __restrict__ p) {
    int nz = 0;
    for (int i = 0; i < 256; i++)
        if ((i & 3) != 0 && p[i] != 0) nz++;
    g_dones_is_byte = (nz > 0) ? 1 : 0;
}
__device__ __forceinline__ bool read_done(const void* dones, int idx, int is_byte) {
    if (is_byte) return ((const unsigned char*)dones)[idx] != 0;
    return ((const int*)dones)[idx] != 0;
}

// ---------------- bf16 split conversions ----------------
__global__ __launch_bounds__(256) void convert_ins_kernel(const float* __restrict__ A) {
    size_t i = ((size_t)blockIdx.x * 256 + threadIdx.x) * 4;
    float4 v = *(const float4*)(A + i);
    __nv_bfloat16 h0 = __float2bfloat16_rn(v.x);
    __nv_bfloat16 h1 = __float2bfloat16_rn(v.y);
    __nv_bfloat16 h2 = __float2bfloat16_rn(v.z);
    __nv_bfloat16 h3 = __float2bfloat16_rn(v.w);
    __nv_bfloat16 l0 = __float2bfloat16_rn(v.x - __bfloat162float(h0));
    __nv_bfloat16 l1 = __float2bfloat16_rn(v.y - __bfloat162float(h1));
    __nv_bfloat16 l2 = __float2bfloat16_rn(v.z - __bfloat162float(h2));
    __nv_bfloat16 l3 = __float2bfloat16_rn(v.w - __bfloat162float(h3));
    __nv_bfloat162* hp = (__nv_bfloat162*)(g_ins_hi + i);
    __nv_bfloat162* lp = (__nv_bfloat162*)(g_ins_lo + i);
    hp[0] = __nv_bfloat162(h0, h1); hp[1] = __nv_bfloat162(h2, h3);
    lp[0] = __nv_bfloat162(l0, l1); lp[1] = __nv_bfloat162(l2, l3);
}

// [K,N3] f32 -> [N3,K] bf16 hi/lo, 32x32 SMEM tile transpose
__global__ __launch_bounds__(256) void convert_w_kernel(
    const float* __restrict__ W, __nv_bfloat16* __restrict__ hi,
    __nv_bfloat16* __restrict__ lo)
{
    __shared__ float tile[32][33];
    const int nb = blockIdx.x * 32;
    const int kb = blockIdx.y * 32;
    const int c = threadIdx.x & 31;
    const int r8 = threadIdx.x >> 5;
#pragma unroll
    for (int s = 0; s < 4; s++) {
        int r = r8 + s * 8;
        tile[r][c] = W[(size_t)(kb + r) * N3 + nb + c];
    }
    __syncthreads();
#pragma unroll
    for (int s = 0; s < 4; s++) {
        int r = r8 + s * 8;
        float v = tile[c][r];
        __nv_bfloat16 h = __float2bfloat16_rn(v);
        __nv_bfloat16 l = __float2bfloat16_rn(v - __bfloat162float(h));
        size_t o = (size_t)(nb + r) * DIM + kb + c;
        hi[o] = h;
        lo[o] = l;
    }
}

// ---------------- HMMA / async primitives ----------------
__device__ __forceinline__ void ldsm_x4(uint32_t addr, uint32_t* r) {
    asm volatile("ldmatrix.sync.aligned.m8n8.x4.shared.b16 {%0,%1,%2,%3}, [%4];"
                 : "=r"(r[0]), "=r"(r[1]), "=r"(r[2]), "=r"(r[3]) : "r"(addr));
}
__device__ __forceinline__ void mma16816(float* c, const uint32_t* a,
                                         uint32_t b0, uint32_t b1) {
    asm volatile(
        "mma.sync.aligned.m16n8k16.row.col.f32.bf16.bf16.f32 "
        "{%0,%1,%2,%3}, {%4,%5,%6,%7}, {%8,%9}, {%0,%1,%2,%3};"
        : "+f"(c[0]), "+f"(c[1]), "+f"(c[2]), "+f"(c[3])
        : "r"(a[0]), "r"(a[1]), "r"(a[2]), "r"(a[3]), "r"(b0), "r"(b1));
}
__device__ __forceinline__ void cp16(uint32_t dst, const void* src) {
    asm volatile("cp.async.cg.shared.global [%0], [%1], 16;"
                 :: "r"(dst), "l"(src));
}
#define CP_COMMIT() asm volatile("cp.async.commit_group;" ::: "memory")

// ---------------------------------------------------------------------------
// HMMA xproj: g_xproj = ins @ W_i + b_i, bf16x3.
// BM=128, BN=256, BK=32; 8 warps, warp tile 64x64; cp.async tile loads.
// ---------------------------------------------------------------------------
#define XSTRIDE 40
#define XA_ELEMS (128 * XSTRIDE)          // 5120 per buffer
#define XB_BASE  (2 * XA_ELEMS)           // 10240
#define XB_ELEMS (256 * XSTRIDE)          // 10240 per buffer
#define XPROJ_SMEM ((XB_BASE + 2 * XB_ELEMS) * 2)   // 61440 B

__global__ __launch_bounds__(256, 1) void gemm_xproj_mma_kernel(
    const float* __restrict__ bias)
{
    extern __shared__ __nv_bfloat16 xsm[];
    const uint32_t smb = smem_u32(xsm);

    const int tid = threadIdx.x;
    const int wid = tid >> 5;
    const int lane = tid & 31;
    const int wm = wid >> 2;            // 0..1 (64 m rows)
    const int wn = wid & 3;             // 0..3 (64 n cols)
    const int bn = blockIdx.x;          // 0..11
    const int bm = blockIdx.y;          // 0..127

    const __nv_bfloat16* Ahi = g_ins_hi + (size_t)bm * 128 * DIM;
    const __nv_bfloat16* Alo = g_ins_lo + (size_t)bm * 128 * DIM;
    const __nv_bfloat16* Bhi = g_wi_hi + (size_t)bn * 256 * DIM;
    const __nv_bfloat16* Blo = g_wi_lo + (size_t)bn * 256 * DIM;

    // per-thread load coords: A 2x16B, B 4x16B per tile
    int arow[2], akc[2], aso[2];
#pragma unroll
    for (int v = 0; v < 2; v++) {
        int u = tid * 2 + v;
        arow[v] = u >> 2; akc[v] = (u & 3) * 8;
        aso[v] = arow[v] * XSTRIDE + akc[v];
    }
    int brow[4], bkc[4], bso[4];
#pragma unroll
    for (int v = 0; v < 4; v++) {
        int u = tid * 4 + v;
        brow[v] = u >> 2; bkc[v] = (u & 3) * 8;
        bso[v] = brow[v] * XSTRIDE + bkc[v];
    }

    const int a_static = (wm * 64 + (lane & 15)) * XSTRIDE + (lane >> 4) * 8;
    const int b_static = (wn * 64 + (lane & 7) + ((lane >> 4) & 1) * 8) * XSTRIDE
                         + ((lane >> 3) & 1) * 8;

    float acc[4][8][4];
#pragma unroll
    for (int i = 0; i < 4; i++)
#pragma unroll
        for (int j = 0; j < 8; j++)
#pragma unroll
            for (int q = 0; q < 4; q++) acc[i][j][q] = 0.f;

    // issue tile kt into buffer buf
    auto issue = [&](int buf, int kt) {
        int pass = kt >> 5;
        int k0 = (kt & 31) * 32;
        const __nv_bfloat16* Ap = (pass < 2) ? Ahi : Alo;
        const __nv_bfloat16* Bp = (pass == 1) ? Blo : Bhi;
        uint32_t abase = smb + (buf * XA_ELEMS) * 2;
        uint32_t bbase = smb + (XB_BASE + buf * XB_ELEMS) * 2;
#pragma unroll
        for (int v = 0; v < 2; v++)
            cp16(abase + aso[v] * 2, Ap + (size_t)arow[v] * DIM + k0 + akc[v]);
#pragma unroll
        for (int v = 0; v < 4; v++)
            cp16(bbase + bso[v] * 2, Bp + (size_t)brow[v] * DIM + k0 + bkc[v]);
        CP_COMMIT();
    };

    issue(0, 0);
    int cur = 0;
    for (int kt = 0; kt < 96; kt++) {
        if (kt + 1 < 96) {
            issue(cur ^ 1, kt + 1);
            asm volatile("cp.async.wait_group 1;" ::: "memory");
        } else {
            asm volatile("cp.async.wait_group 0;" ::: "memory");
        }
        __syncthreads();

        const uint32_t a_base = smb + (cur * XA_ELEMS + a_static) * 2;
        const uint32_t b_base = smb + (XB_BASE + cur * XB_ELEMS + b_static) * 2;
#pragma unroll
        for (int ks = 0; ks < 2; ks++) {
            uint32_t af[4][4], bfr[4][4];
#pragma unroll
            for (int i = 0; i < 4; i++)
                ldsm_x4(a_base + (i * 16 * XSTRIDE + ks * 16) * 2, af[i]);
#pragma unroll
            for (int jj = 0; jj < 4; jj++)
                ldsm_x4(b_base + (jj * 16 * XSTRIDE + ks * 16) * 2, bfr[jj]);
#pragma unroll
            for (int i = 0; i < 4; i++)
#pragma unroll
                for (int j = 0; j < 8; j++)
                    mma16816(acc[i][j], af[i],
                             bfr[j >> 1][(j & 1) * 2], bfr[j >> 1][(j & 1) * 2 + 1]);
        }
        __syncthreads();
        cur ^= 1;
    }

    const int groupID = lane >> 2, tig = lane & 3;
#pragma unroll
    for (int i = 0; i < 4; i++) {
        int mrow = bm * 128 + wm * 64 + i * 16 + groupID;
        float* row0 = g_xproj + (size_t)mrow * N3;
        float* row1 = g_xproj + (size_t)(mrow + 8) * N3;
#pragma unroll
        for (int j = 0; j < 8; j++) {
            int ncol = bn * 256 + wn * 64 + j * 8 + tig * 2;
            float2 bv = *(const float2*)&bias[ncol];
            float2 o0, o1;
            o0.x = acc[i][j][0] + bv.x; o0.y = acc[i][j][1] + bv.y;
            o1.x = acc[i][j][2] + bv.x; o1.y = acc[i][j][3] + bv.y;
            *(float2*)&row0[ncol] = o0;
            *(float2*)&row1[ncol] = o1;
        }
    }
}

// ---------------------------------------------------------------------------
// Grid barrier: syncthreads + leader release-atomic / pure-spin acquire poll.
// count and epoch on separate 256B lines.
// ---------------------------------------------------------------------------
__device__ __forceinline__ void grid_barrier(unsigned* s_epoch, bool last) {
    __syncthreads();
    if (threadIdx.x == 0) {
        unsigned my = *s_epoch;
        unsigned prev;
        asm volatile("atom.release.gpu.add.u32 %0, [%1], 1;"
                     : "=r"(prev) : "l"(&g_bar[0]) : "memory");
        if (prev == NCTA - 1) {
            g_bar[0] = 0;
            asm volatile("st.release.gpu.u32 [%0], %1;"
                         :: "l"(&g_bar[64]), "r"(last ? 0u : (my + 1u))
                         : "memory");
        } else {
            unsigned e;
            do {
                asm volatile("ld.acquire.gpu.u32 %0, [%1];"
                             : "=r"(e) : "l"(&g_bar[64]) : "memory");
            } while (e == my);
        }
        *s_epoch = my + 1u;
    }
    __syncthreads();
}

// ---------------------------------------------------------------------------
// Persistent scan (R8 structure): split-K 4-way, W slice resident, 2 barriers.
// h carried in registers for phase B; hi/lo splits published for phase A.
// ---------------------------------------------------------------------------
#define XS 264
#define SM_HHI 0
#define SM_HLO (64 * XS)
#define SM_WHI (128 * XS)
#define SM_WLO (224 * XS)
#define SCAN_SMEM (320 * XS * 2)   // 168960 B

__global__ __launch_bounds__(NTHR, 1) void scan_kernel(
    const float* __restrict__ hiddens,
    const void*  __restrict__ dones,
    const float* __restrict__ init_carry,
    const float* __restrict__ b_hn,
    float* __restrict__ out)
{
    extern __shared__ __nv_bfloat16 sm[];
    __shared__ unsigned s_epoch;

    const int tid = threadIdx.x;
    const int cta = blockIdx.x;
    const int bn = cta & 31;             // n-slice (96 gate cols)
    const int kidx = cta >> 5;           // k-chunk (256)
    const int kbase = kidx * 256;
    const int wid = tid >> 5;
    const int lane = tid & 31;
    const int wm = wid >> 1;             // m16 tile
    const int wn = wid & 1;              // n48 tile
    const int is_byte = g_dones_is_byte;
    float* ys = out + (size_t)BSZ * DIM;

    if (tid == 0) s_epoch = 0;

    // phase-B static mapping: one b per CTA, 512 d columns
    const int pb_b = cta >> 1;
    const int pb_d = (cta & 1) * 512 + tid * 2;
    const float2 bh2 = *(const float2*)&b_hn[pb_d];

    // W_h slice -> SMEM once (hi+lo)
    for (int i = tid; i < 96 * 32; i += NTHR) {
        int row = i >> 5;
        int kc = (i & 31) * 8;
        size_t go = (size_t)(bn * 96 + row) * DIM + kbase + kc;
        *(uint4*)&sm[SM_WHI + row * XS + kc] = *(const uint4*)&g_wh_hi[go];
        *(uint4*)&sm[SM_WLO + row * XS + kc] = *(const uint4*)&g_wh_lo[go];
    }

    // init h (t=0 reset applied): register h + published bf16 splits
    float2 hprev;
    {
        bool dn = read_done(dones, pb_b, is_byte);
        const float* src = dn ? (hiddens + (size_t)pb_b * DIM)
                              : (init_carry + (size_t)pb_b * DIM);
        hprev = *(const float2*)&src[pb_d];
        __nv_bfloat16 h0 = __float2bfloat16_rn(hprev.x);
        __nv_bfloat16 h1 = __float2bfloat16_rn(hprev.y);
        __nv_bfloat16 l0 = __float2bfloat16_rn(hprev.x - __bfloat162float(h0));
        __nv_bfloat16 l1 = __float2bfloat16_rn(hprev.y - __bfloat162float(h1));
        *(__nv_bfloat162*)&g_hh[pb_b * DIM + pb_d] = __nv_bfloat162(h0, h1);
        *(__nv_bfloat162*)&g_hl[pb_b * DIM + pb_d] = __nv_bfloat162(l0, l1);
    }
    grid_barrier(&s_epoch, false);

    const int a_off = (wm * 16 + (lane & 15)) * XS + (lane >> 4) * 8;
    const int b_off = (wn * 48 + (lane & 7) + ((lane >> 4) & 1) * 8) * XS
                      + ((lane >> 3) & 1) * 8;
    const int groupID = lane >> 2, tig = lane & 3;

    for (int t = 0; t < T_STEPS; t++) {
        // prefetch everything phase B needs (hides L2 latency under phase A)
        const float* xp = g_xproj + ((size_t)t * BSZ + pb_b) * N3;
        float2 xr = __ldcg((const float2*)&xp[pb_d]);
        float2 xz = __ldcg((const float2*)&xp[DIM + pb_d]);
        float2 xn = __ldcg((const float2*)&xp[2 * DIM + pb_d]);
        float2 hid_nx = make_float2(0.f, 0.f);
        int dn_nx = 0;
        if (t + 1 < T_STEPS) {
            dn_nx = read_done(dones, (t + 1) * BSZ + pb_b, is_byte) ? 1 : 0;
            hid_nx = __ldcg((const float2*)
                            &hiddens[((size_t)(t + 1) * BSZ + pb_b) * DIM + pb_d]);
        }

        // ---- stage h chunk hi/lo ----
        for (int i = tid; i < 64 * 32; i += NTHR) {
            int row = i >> 5;
            int kc = (i & 31) * 8;
            size_t go = (size_t)row * DIM + kbase + kc;
            *(uint4*)&sm[SM_HHI + row * XS + kc] = __ldcg((const uint4*)&g_hh[go]);
            *(uint4*)&sm[SM_HLO + row * XS + kc] = __ldcg((const uint4*)&g_hl[go]);
        }
        __syncthreads();

        // ---- phase A: 3-pass HMMA, warp tile m16 x n48 ----
        float acc[6][4];
#pragma unroll
        for (int j = 0; j < 6; j++)
#pragma unroll
            for (int q = 0; q < 4; q++) acc[j][q] = 0.f;

#pragma unroll
        for (int pass = 0; pass < 3; pass++) {
            const uint32_t ab = smem_u32(sm) +
                ((pass == 1 ? SM_HLO : SM_HHI) + a_off) * 2;
            const uint32_t bb = smem_u32(sm) +
                ((pass == 2 ? SM_WLO : SM_WHI) + b_off) * 2;
#pragma unroll 4
            for (int ks = 0; ks < 16; ks++) {
                uint32_t af[4], bfr[3][4];
                ldsm_x4(ab + ks * 32, af);
#pragma unroll
                for (int jt = 0; jt < 3; jt++)
                    ldsm_x4(bb + jt * 16 * XS * 2 + ks * 32, bfr[jt]);
#pragma unroll
                for (int j = 0; j < 6; j++)
                    mma16816(acc[j], af,
                             bfr[j >> 1][(j & 1) * 2], bfr[j >> 1][(j & 1) * 2 + 1]);
            }
        }

        // write f32 partials
        {
            int b0r = wm * 16 + groupID;
            float* gp0 = g_part + ((size_t)(kidx * BSZ + b0r)) * N3 + bn * 96;
            float* gp1 = gp0 + (size_t)8 * N3;
#pragma unroll
            for (int j = 0; j < 6; j++) {
                int col = wn * 48 + j * 8 + tig * 2;
                *(float2*)&gp0[col] = make_float2(acc[j][0], acc[j][1]);
                *(float2*)&gp1[col] = make_float2(acc[j][2], acc[j][3]);
            }
        }
        grid_barrier(&s_epoch, false);

        // ---- phase B: reduce partials + gates ----
        {
            float2 pr = {0.f, 0.f}, pz = {0.f, 0.f}, pn = {0.f, 0.f};
#pragma unroll
            for (int k = 0; k < 4; k++) {
                const float* g = g_part + (size_t)(k * BSZ + pb_b) * N3;
                float2 v;
                v = __ldcg((const float2*)&g[pb_d]);            pr.x += v.x; pr.y += v.y;
                v = __ldcg((const float2*)&g[DIM + pb_d]);      pz.x += v.x; pz.y += v.y;
                v = __ldcg((const float2*)&g[2 * DIM + pb_d]);  pn.x += v.x; pn.y += v.y;
            }

            float rx = 1.f / (1.f + __expf(-(xr.x + pr.x)));
            float ry = 1.f / (1.f + __expf(-(xr.y + pr.y)));
            float zx = 1.f / (1.f + __expf(-(xz.x + pz.x)));
            float zy = 1.f / (1.f + __expf(-(xz.y + pz.y)));
            float nx = tanhf(xn.x + rx * (pn.x + bh2.x));
            float ny = tanhf(xn.y + ry * (pn.y + bh2.y));
            float2 hnew;
            hnew.x = (1.f - zx) * nx + zx * hprev.x;
            hnew.y = (1.f - zy) * ny + zy * hprev.y;

            *(float2*)&ys[((size_t)t * BSZ + pb_b) * DIM + pb_d] = hnew;
            if (t == T_STEPS - 1) {
                *(float2*)&out[pb_b * DIM + pb_d] = hnew;
            } else {
                float2 he = dn_nx ? hid_nx : hnew;
                hprev = he;
                __nv_bfloat16 h0 = __float2bfloat16_rn(he.x);
                __nv_bfloat16 h1 = __float2bfloat16_rn(he.y);
                __nv_bfloat16 l0 = __float2bfloat16_rn(he.x - __bfloat162float(h0));
                __nv_bfloat16 l1 = __float2bfloat16_rn(he.y - __bfloat162float(h1));
                *(__nv_bfloat162*)&g_hh[pb_b * DIM + pb_d] = __nv_bfloat162(h0, h1);
                *(__nv_bfloat162*)&g_hl[pb_b * DIM + pb_d] = __nv_bfloat162(l0, l1);
            }
        }
        grid_barrier(&s_epoch, t == T_STEPS - 1);
    }
}

// ---------------------------------------------------------------------------
extern "C" void kernel_launch(void* const* d_in, const int* in_sizes, int n_in,
                              void* d_out, int out_size) {
    const float* ins        = (const float*)d_in[0];
    const float* hiddens    = (const float*)d_in[1];
    const void*  dones      = d_in[2];
    const float* init_carry = (const float*)d_in[3];
    const float* W_i        = (const float*)d_in[4];
    const float* W_h        = (const float*)d_in[5];
    const float* b_i        = (const float*)d_in[6];
    const float* b_hn       = (const float*)d_in[7];
    float* out = (float*)d_out;

    __nv_bfloat16 *wi_hi_p, *wi_lo_p, *wh_hi_p, *wh_lo_p;
    cudaGetSymbolAddress((void**)&wi_hi_p, g_wi_hi);
    cudaGetSymbolAddress((void**)&wi_lo_p, g_wi_lo);
    cudaGetSymbolAddress((void**)&wh_hi_p, g_wh_hi);
    cudaGetSymbolAddress((void**)&wh_lo_p, g_wh_lo);

    cudaFuncSetAttribute(scan_kernel,
                         cudaFuncAttributeMaxDynamicSharedMemorySize, SCAN_SMEM);
    cudaFuncSetAttribute(gemm_xproj_mma_kernel,
                         cudaFuncAttributeMaxDynamicSharedMemorySize, XPROJ_SMEM);

    detect_dones_kernel<<<1, 1>>>((const unsigned char*)dones);

    convert_ins_kernel<<<(int)(((size_t)M_TOTAL * DIM / 4) / 256), 256>>>(ins);
    {
        dim3 gw(N3 / 32, DIM / 32);
        convert_w_kernel<<<gw, 256>>>(W_i, wi_hi_p, wi_lo_p);
        convert_w_kernel<<<gw, 256>>>(W_h, wh_hi_p, wh_lo_p);
    }

    {
        dim3 grid(N3 / 256, M_TOTAL / 128);   // (12, 128)
        gemm_xproj_mma_kernel<<<grid, 256, XPROJ_SMEM>>>(b_i);
    }

    scan_kernel<<<NCTA, NTHR, SCAN_SMEM>>>(hiddens, dones, init_carry, b_hn, out);
}